// round 4
// baseline (speedup 1.0000x reference)
#include <cuda_runtime.h>
#include <math.h>

#define NPROTO  10
#define NCLS    10
#define NPATCH  196
#define NPAIR   98
#define NFEAT   1960
#define BIMG    8192

typedef unsigned long long u64;

// ---- packed f32x2 helpers ---------------------------------------------------
__device__ __forceinline__ u64 pk2(float lo, float hi) {
    u64 r; asm("mov.b64 %0, {%1,%2};" : "=l"(r) : "f"(lo), "f"(hi)); return r;
}
__device__ __forceinline__ u64 fma2(u64 a, u64 b, u64 c) {
    u64 d; asm("fma.rn.f32x2 %0, %1, %2, %3;" : "=l"(d) : "l"(a), "l"(b), "l"(c)); return d;
}
__device__ __forceinline__ u64 mul2(u64 a, u64 b) {
    u64 d; asm("mul.rn.f32x2 %0, %1, %2;" : "=l"(d) : "l"(a), "l"(b)); return d;
}
__device__ __forceinline__ float2 up2(u64 a) {
    float2 f; asm("mov.b64 {%0,%1}, %2;" : "=f"(f.x), "=f"(f.y) : "l"(a)); return f;
}

// smem layout (floats):
//   sW   [0, 19600)         W[c][p][patch]
//   sPc2 [19600, 19680)     40 x float2 dup (cos(proto/2))
//   sPs2 [19680, 19760)     40 x float2 dup (sin(proto/2))
//   sred [19760, 30000)     [16 warps][10 cls][64 img]
//   sfin [30000, 30640)     [64 img][10 cls]
#define SM_FLOATS 30640

// ---------------------------------------------------------------------------
// Fully fused: features + class GEMM + 16-warp reduce + log_softmax.
// Grid 128 x 512. CTA owns 64 images; lane owns 2 (rp pair, f32x2-packed).
// Warp w covers patch-pairs [ps, ps+np): warps 0,1 -> 7 pairs, others 6 (=98).
// Patch pair (2q, 2q+1) is always within one image row -> 2x aligned LDG.128
// fetch all 8 pixels per image.
// ---------------------------------------------------------------------------
__global__ void __launch_bounds__(512, 1)
quanv_fused(const float* __restrict__ x,
            const float* __restrict__ proto,
            const float* __restrict__ W,
            const float* __restrict__ bias,
            float* __restrict__ out)
{
    extern __shared__ float sm[];
    float*  sW   = sm;
    float2* sPc2 = reinterpret_cast<float2*>(sm + 19600);
    float2* sPs2 = reinterpret_cast<float2*>(sm + 19680);
    float*  sred = sm + 19760;
    float*  sfin = sm + 30000;

    const int tid = threadIdx.x;

    // stage W (19600 floats = 4900 float4) and proto sincos splats
    {
        const float4* W4  = reinterpret_cast<const float4*>(W);
        float4*       sW4 = reinterpret_cast<float4*>(sW);
        #pragma unroll
        for (int i = tid; i < 4900; i += 512) sW4[i] = W4[i];
        if (tid < NPROTO * 4) {
            float s, c; __sincosf(0.5f * proto[tid], &s, &c);
            sPc2[tid] = make_float2(c, c);
            sPs2[tid] = make_float2(s, s);
        }
    }
    __syncthreads();

    const int w    = tid >> 5;
    const int lane = tid & 31;
    const int imgbase = blockIdx.x * 64;

    const float* xr0 = x + (size_t)(imgbase + lane     ) * 784;  // rp=0 lo
    const float* xr1 = x + (size_t)(imgbase + lane + 32) * 784;  // rp=0 hi? no: rp index
    // lane's two images: imgA = base+lane (acc[rp] halves are patch halves;
    // rp selects image): rp=0 -> imgA, rp=1 -> imgB = base+lane+32.

    const int ps = w * 6 + min(w, 2);          // pair start
    const int np = 6 + (w < 2 ? 1 : 0);        // pair count

    u64 acc[2][NCLS];
    #pragma unroll
    for (int rp = 0; rp < 2; ++rp)
        #pragma unroll
        for (int c = 0; c < NCLS; ++c) acc[rp][c] = 0ULL;

    for (int q = ps; q < ps + np; ++q) {
        const int pa  = 2 * q;
        const int pr  = pa / 14;
        const int pc  = pa - pr * 14;          // even
        const int off = pr * 56 + pc * 2;      // 16B-aligned float index

        // 8 pixels per image covering patches (pa, pa+1): two LDG.128 each
        u64 cxp[2][4], sxp[2][4];
        const float* xr[2] = { xr0, xr1 };
        #pragma unroll
        for (int rp = 0; rp < 2; ++rp) {
            float4 vt = *reinterpret_cast<const float4*>(xr[rp] + off);
            float4 vb = *reinterpret_cast<const float4*>(xr[rp] + off + 28);
            float c0a,s0a,c0b,s0b,c1a,s1a,c1b,s1b;
            float c2a,s2a,c2b,s2b,c3a,s3a,c3b,s3b;
            __sincosf(0.5f * vt.x, &s0a, &c0a);  // pa px0
            __sincosf(0.5f * vt.z, &s0b, &c0b);  // pb px0
            __sincosf(0.5f * vt.y, &s1a, &c1a);  // pa px1
            __sincosf(0.5f * vt.w, &s1b, &c1b);  // pb px1
            __sincosf(0.5f * vb.x, &s2a, &c2a);  // pa px2
            __sincosf(0.5f * vb.z, &s2b, &c2b);  // pb px2
            __sincosf(0.5f * vb.y, &s3a, &c3a);  // pa px3
            __sincosf(0.5f * vb.w, &s3b, &c3b);  // pb px3
            cxp[rp][0] = pk2(c0a, c0b);  sxp[rp][0] = pk2(s0a, s0b);
            cxp[rp][1] = pk2(c1a, c1b);  sxp[rp][1] = pk2(s1a, s1b);
            cxp[rp][2] = pk2(c2a, c2b);  sxp[rp][2] = pk2(s2a, s2b);
            cxp[rp][3] = pk2(c3a, c3b);  sxp[rp][3] = pk2(s3a, s3b);
        }

        const float* wbase = sW + pa;          // + c*1960 + p*196 (even -> 8B aligned)

        #pragma unroll
        for (int p = 0; p < NPROTO; ++p) {
            ulonglong2 cyA = *reinterpret_cast<const ulonglong2*>(&sPc2[p * 4]);
            ulonglong2 cyB = *reinterpret_cast<const ulonglong2*>(&sPc2[p * 4 + 2]);
            ulonglong2 syA = *reinterpret_cast<const ulonglong2*>(&sPs2[p * 4]);
            ulonglong2 syB = *reinterpret_cast<const ulonglong2*>(&sPs2[p * 4 + 2]);

            u64 kq[2];
            #pragma unroll
            for (int rp = 0; rp < 2; ++rp) {
                // cos((x-y)/2) = cos(x/2)cos(y/2) + sin(x/2)sin(y/2); 2 patches/op
                u64 t0 = fma2(cxp[rp][0], cyA.x, mul2(sxp[rp][0], syA.x));
                u64 t1 = fma2(cxp[rp][1], cyA.y, mul2(sxp[rp][1], syA.y));
                u64 t2 = fma2(cxp[rp][2], cyB.x, mul2(sxp[rp][2], syB.x));
                u64 t3 = fma2(cxp[rp][3], cyB.y, mul2(sxp[rp][3], syB.y));
                kq[rp] = mul2(mul2(t0, t1), mul2(t2, t3)) & 0x7FFFFFFF7FFFFFFFULL;
            }

            const float* wp = wbase + p * NPATCH;  // warp-uniform
            #pragma unroll
            for (int c = 0; c < NCLS; ++c) {
                // (W[c,p,pa], W[c,p,pa+1]) in one broadcast LDS.64
                u64 wv = *reinterpret_cast<const u64*>(wp + c * NFEAT);
                acc[0][c] = fma2(kq[0], wv, acc[0][c]);
                acc[1][c] = fma2(kq[1], wv, acc[1][c]);
            }
        }
    }

    // collapse patch halves, deposit per-warp partials: sred[w][c][rp*32+lane]
    #pragma unroll
    for (int rp = 0; rp < 2; ++rp)
        #pragma unroll
        for (int c = 0; c < NCLS; ++c) {
            float2 f = up2(acc[rp][c]);
            sred[(w * NCLS + c) * 64 + rp * 32 + lane] = f.x + f.y;
        }
    __syncthreads();

    // reduce 16 warps: 640 threads? we have 512; do 2 classes per thread for c>=... 
    // simpler: 512 threads cover (img 0..63) x (c 0..7), then 128 threads cover c 8,9.
    {
        int im = tid & 63;
        int c  = tid >> 6;          // 0..7
        float s = bias[c];
        #pragma unroll
        for (int ww = 0; ww < 16; ++ww) s += sred[(ww * NCLS + c) * 64 + im];
        sfin[im * NCLS + c] = s;
        if (tid < 128) {
            int im2 = tid & 63;
            int c2  = 8 + (tid >> 6);
            float s2 = bias[c2];
            #pragma unroll
            for (int ww = 0; ww < 16; ++ww) s2 += sred[(ww * NCLS + c2) * 64 + im2];
            sfin[im2 * NCLS + c2] = s2;
        }
    }
    __syncthreads();

    // log_softmax + store: one thread per image
    if (tid < 64) {
        float logit[NCLS];
        #pragma unroll
        for (int c = 0; c < NCLS; ++c) logit[c] = sfin[tid * NCLS + c];
        float m = logit[0];
        #pragma unroll
        for (int c = 1; c < NCLS; ++c) m = fmaxf(m, logit[c]);
        float ssum = 0.f;
        #pragma unroll
        for (int c = 0; c < NCLS; ++c) ssum += expf(logit[c] - m);
        const float lse = m + logf(ssum);
        float* op = out + (size_t)(imgbase + tid) * NCLS;
        #pragma unroll
        for (int c = 0; c < NCLS; ++c) op[c] = logit[c] - lse;
    }
}

// ---------------------------------------------------------------------------
extern "C" void kernel_launch(void* const* d_in, const int* in_sizes, int n_in,
                              void* d_out, int out_size)
{
    const float* x     = (const float*)d_in[0];  // (8192, 784)
    const float* proto = (const float*)d_in[1];  // (10, 4)
    const float* W     = (const float*)d_in[2];  // (10, 1960)
    const float* bias  = (const float*)d_in[3];  // (10,)
    float* out = (float*)d_out;                  // (8192, 10)

    const int smem_bytes = SM_FLOATS * (int)sizeof(float);   // 122,560 B
    cudaFuncSetAttribute(quanv_fused,
                         cudaFuncAttributeMaxDynamicSharedMemorySize, smem_bytes);

    quanv_fused<<<BIMG / 64, 512, smem_bytes>>>(x, proto, W, bias, out);
}